// round 11
// baseline (speedup 1.0000x reference)
#include <cuda_runtime.h>
#include <cuda_fp16.h>
#include <cuda_bf16.h>
#include <mma.h>
#include <math.h>
#include <float.h>

using namespace nvcuda;

#define NN 4096
#define FF 320
#define FH 160          // FF/2 (half2 columns)
#define MAXDEG 256
#define RPB 4           // rows per attn block
#define TPW 80          // threads per row (2 teams)
#define TPR 40          // threads per team (40 * uint4 = 320 floats)
#define NCB 5           // GEMM column blocks (FF/BN)

#define BM 64
#define BN 64
#define BK 16
#define LDA 72          // smem ld for bf16 tiles
#define LDC (BN + 4)    // epilogue staging ld (floats)

// padded-row offsets for the 9 pre-split weights
#define WOFF_START   0
#define WOFF_DOWN0   336
#define WOFF_DOWN1   672
#define WOFF_BOTTOM  1008
#define WOFF_UP0     1344
#define WOFF_UP1     1680
#define WOFF_END     2016     // pad 656
#define WOFF_UNP0    2672
#define WOFF_UNP1    2992
#define WROWS_TOTAL  3312

// ---------------- scratch (static __device__ globals; no allocations) ----------------
__device__ __half g_WhH[NN * FF];
__device__ __nv_bfloat16 g_WH[WROWS_TOTAL * FF];
__device__ __nv_bfloat16 g_WL[WROWS_TOTAL * FF];
__device__ float g_org[NN * FF];
__device__ float g_D0[NN * FF];
__device__ float g_D1[NN * FF];
__device__ float g_bA[NN * FF];
__device__ float g_bB[NN * FF];
__device__ float g_cent[NN];
__device__ float g_sp1[NCB * NN];
__device__ float g_sp2[NCB * NN];
__device__ float g_sc[NN];
__device__ int g_cols[NN * MAXDEG];
__device__ int g_deg[NN];
__device__ int g_idp[NN];
__device__ int g_p1[NN];
__device__ int g_p2[NN];
__device__ int g_pi1[NN];
__device__ int g_pi2[NN];
__device__ int g_i0[NN];
__device__ int g_i1[NN];

// ---------------- adjacency ELL build + degree centrality + identity perm ----------------
__global__ void build_adj(const float* __restrict__ A, int* __restrict__ cols,
                          int* __restrict__ deg, float* __restrict__ cent,
                          int* __restrict__ idp) {
    int warp = (blockIdx.x * blockDim.x + threadIdx.x) >> 5;
    int lane = threadIdx.x & 31;
    if (warp >= NN) return;
    long rowoff = (long)warp * NN;
    float sum = 0.f;
    int base = 0;
    for (int c0 = 0; c0 < NN; c0 += 32) {
        float v = A[rowoff + c0 + lane];
        sum += v;
        unsigned m = __ballot_sync(0xffffffffu, v > 0.f);
        if (v > 0.f) {
            int pos = base + __popc(m & ((1u << lane) - 1u));
            if (pos < MAXDEG) cols[(long)warp * MAXDEG + pos] = c0 + lane;
        }
        base += __popc(m);
    }
    for (int o = 16; o; o >>= 1) sum += __shfl_xor_sync(0xffffffffu, sum, o);
    if (lane == 0) {
        deg[warp] = base < MAXDEG ? base : MAXDEG;
        cent[warp] = sum / (float)(NN - 1);
        idp[warp] = warp;
    }
}

// ---------------- batched weight split (hi/lo bf16, zero-padded rows, opt transpose) ----------------
struct WTable {
    const float* src[9];
    int rows[9];
    int rowsPad[9];
    int trans[9];
    int dstOff[9];
};

__global__ void split_weights(WTable wt, __nv_bfloat16* __restrict__ WH,
                              __nv_bfloat16* __restrict__ WL) {
    int w = blockIdx.y;
    int idx = blockIdx.x * blockDim.x + threadIdx.x;
    int total = wt.rowsPad[w] * FF;
    if (idx >= total) return;
    int r = idx / FF, c = idx - r * FF;
    float v = 0.f;
    if (r < wt.rows[w])
        v = wt.trans[w] ? wt.src[w][(long)c * FF + r] : wt.src[w][(long)r * FF + c];
    __nv_bfloat16 h = __float2bfloat16(v);
    __nv_bfloat16 l = __float2bfloat16(v - __bfloat162float(h));
    long o = (long)(wt.dstOff[w] + r) * FF + c;
    WH[o] = h;
    WL[o] = l;
}

// ---------------- WMMA GEMM (double-buffered): CH(half) = [X1|X2|cent*nc] @ W ----------------
__global__ __launch_bounds__(128) void gemm_cat(
    const float* __restrict__ X1, int K1,
    const float* __restrict__ X2, int K2,
    int nc, const float* __restrict__ cent,
    const __nv_bfloat16* __restrict__ WH, const __nv_bfloat16* __restrict__ WL,
    int Ktot, int nT,
    __half* __restrict__ CH, const float* __restrict__ av,
    float* __restrict__ sp1, float* __restrict__ sp2) {
    __shared__ __nv_bfloat16 AsH[2][BK][LDA], AsL[2][BK][LDA];
    __shared__ __nv_bfloat16 BsH[2][BK][LDA], BsL[2][BK][LDA];
    __shared__ float Cs[BM][LDC];
    int tid = threadIdx.x;
    int row0 = blockIdx.y * BM;
    int col0 = blockIdx.x * BN;
    int K12 = K1 + K2;

    int wid = tid >> 5;
    int wm = (wid >> 1) * 32;
    int wn = (wid & 1) * 32;

    wmma::fragment<wmma::accumulator, 16, 16, 16, float> acc[2][2];
#pragma unroll
    for (int i = 0; i < 2; i++)
#pragma unroll
        for (int j = 0; j < 2; j++) wmma::fill_fragment(acc[i][j], 0.f);

    int a_kk = tid & 15, a_m0 = tid >> 4;
    int b_kk = tid >> 3, b_n0 = (tid & 7) * 8;

    float pa[8];
    uint4 pbH, pbL;

#pragma unroll
    for (int l = 0; l < 8; l++) {
        int m = a_m0 + l * 8;
        int k = a_kk;
        int r = row0 + m;
        float v = 0.f;
        if (k < K1) v = X1[(long)r * K1 + k];
        else if (k < K12) v = X2[(long)r * K2 + (k - K1)];
        else if (k < Ktot) v = cent[r];
        pa[l] = v;
    }
    pbH = *(const uint4*)&WH[(long)b_kk * FF + col0 + b_n0];
    pbL = *(const uint4*)&WL[(long)b_kk * FF + col0 + b_n0];
#pragma unroll
    for (int l = 0; l < 8; l++) {
        __nv_bfloat16 h = __float2bfloat16(pa[l]);
        AsH[0][a_kk][a_m0 + l * 8] = h;
        AsL[0][a_kk][a_m0 + l * 8] = __float2bfloat16(pa[l] - __bfloat162float(h));
    }
    *(uint4*)&BsH[0][b_kk][b_n0] = pbH;
    *(uint4*)&BsL[0][b_kk][b_n0] = pbL;
    __syncthreads();

    for (int t = 0; t < nT; t++) {
        int buf = t & 1;
        bool hasNext = (t + 1 < nT);
        if (hasNext) {
            int k0 = (t + 1) * BK;
#pragma unroll
            for (int l = 0; l < 8; l++) {
                int m = a_m0 + l * 8;
                int k = k0 + a_kk;
                int r = row0 + m;
                float v = 0.f;
                if (k < K1) v = X1[(long)r * K1 + k];
                else if (k < K12) v = X2[(long)r * K2 + (k - K1)];
                else if (k < Ktot) v = cent[r];
                pa[l] = v;
            }
            pbH = *(const uint4*)&WH[(long)(k0 + b_kk) * FF + col0 + b_n0];
            pbL = *(const uint4*)&WL[(long)(k0 + b_kk) * FF + col0 + b_n0];
        }
        {
            wmma::fragment<wmma::matrix_a, 16, 16, 16, __nv_bfloat16, wmma::col_major> aH[2], aL[2];
            wmma::fragment<wmma::matrix_b, 16, 16, 16, __nv_bfloat16, wmma::row_major> bH[2], bL[2];
#pragma unroll
            for (int i = 0; i < 2; i++) {
                wmma::load_matrix_sync(aH[i], &AsH[buf][0][wm + 16 * i], LDA);
                wmma::load_matrix_sync(aL[i], &AsL[buf][0][wm + 16 * i], LDA);
            }
#pragma unroll
            for (int j = 0; j < 2; j++) {
                wmma::load_matrix_sync(bH[j], &BsH[buf][0][wn + 16 * j], LDA);
                wmma::load_matrix_sync(bL[j], &BsL[buf][0][wn + 16 * j], LDA);
            }
#pragma unroll
            for (int i = 0; i < 2; i++)
#pragma unroll
                for (int j = 0; j < 2; j++) {
                    wmma::mma_sync(acc[i][j], aH[i], bH[j], acc[i][j]);
                    wmma::mma_sync(acc[i][j], aH[i], bL[j], acc[i][j]);
                    wmma::mma_sync(acc[i][j], aL[i], bH[j], acc[i][j]);
                }
        }
        if (hasNext) {
            int nbuf = 1 - buf;
#pragma unroll
            for (int l = 0; l < 8; l++) {
                __nv_bfloat16 h = __float2bfloat16(pa[l]);
                AsH[nbuf][a_kk][a_m0 + l * 8] = h;
                AsL[nbuf][a_kk][a_m0 + l * 8] = __float2bfloat16(pa[l] - __bfloat162float(h));
            }
            *(uint4*)&BsH[nbuf][b_kk][b_n0] = pbH;
            *(uint4*)&BsL[nbuf][b_kk][b_n0] = pbL;
            __syncthreads();
        }
    }
#pragma unroll
    for (int i = 0; i < 2; i++)
#pragma unroll
        for (int j = 0; j < 2; j++)
            wmma::store_matrix_sync(&Cs[wm + 16 * i][wn + 16 * j], acc[i][j], LDC,
                                    wmma::mem_row_major);
    __syncthreads();

    int tx = tid & 15, ty = tid >> 4;
    float a1v[4], a2v[4];
#pragma unroll
    for (int j = 0; j < 4; j++) {
        int c = col0 + tx * 4 + j;
        a1v[j] = __ldg(av + c);
        a2v[j] = __ldg(av + FF + c);
    }
#pragma unroll
    for (int i = 0; i < 8; i++) {
        int m = ty * 8 + i;
        int r = row0 + m;
        float c0v = Cs[m][tx * 4 + 0];
        float c1v = Cs[m][tx * 4 + 1];
        float c2v = Cs[m][tx * 4 + 2];
        float c3v = Cs[m][tx * 4 + 3];
        long base = (long)r * FF + col0 + tx * 4;
        __half2* hdst = (__half2*)(CH + base);
        hdst[0] = __floats2half2_rn(c0v, c1v);
        hdst[1] = __floats2half2_rn(c2v, c3v);
        float p1 = c0v * a1v[0] + c1v * a1v[1] + c2v * a1v[2] + c3v * a1v[3];
        float p2 = c0v * a2v[0] + c1v * a2v[1] + c2v * a2v[2] + c3v * a2v[3];
#pragma unroll
        for (int o = 8; o; o >>= 1) {
            p1 += __shfl_down_sync(0xffffffffu, p1, o);
            p2 += __shfl_down_sync(0xffffffffu, p2, o);
        }
        if (tx == 0) {
            sp1[blockIdx.x * NN + r] = p1;
            sp2[blockIdx.x * NN + r] = p2;
        }
    }
}

// ---------------- WMMA unpool: out[idx[i]][j] = X[i][j]*sigmoid((X@W^T)[i][j]+b[j]) ----------------
__global__ __launch_bounds__(128) void gemm_unpool(
    const float* __restrict__ X,
    const __nv_bfloat16* __restrict__ WH, const __nv_bfloat16* __restrict__ WL,
    const float* __restrict__ b, const int* __restrict__ idxArr,
    float* __restrict__ out) {
    __shared__ __nv_bfloat16 AsH[2][BK][LDA], AsL[2][BK][LDA];
    __shared__ __nv_bfloat16 BsH[2][BK][LDA], BsL[2][BK][LDA];
    __shared__ float Cs[BM][LDC];
    int tid = threadIdx.x;
    int row0 = blockIdx.y * BM;
    int col0 = blockIdx.x * BN;
    const int nT = FF / BK;   // 20

    int wid = tid >> 5;
    int wm = (wid >> 1) * 32;
    int wn = (wid & 1) * 32;

    wmma::fragment<wmma::accumulator, 16, 16, 16, float> acc[2][2];
#pragma unroll
    for (int i = 0; i < 2; i++)
#pragma unroll
        for (int j = 0; j < 2; j++) wmma::fill_fragment(acc[i][j], 0.f);

    int a_kk = tid & 15, a_m0 = tid >> 4;
    int b_kk = tid >> 3, b_n0 = (tid & 7) * 8;

    float pa[8];
    uint4 pbH, pbL;
#pragma unroll
    for (int l = 0; l < 8; l++)
        pa[l] = X[(long)(row0 + a_m0 + l * 8) * FF + a_kk];
    pbH = *(const uint4*)&WH[(long)b_kk * FF + col0 + b_n0];
    pbL = *(const uint4*)&WL[(long)b_kk * FF + col0 + b_n0];
#pragma unroll
    for (int l = 0; l < 8; l++) {
        __nv_bfloat16 h = __float2bfloat16(pa[l]);
        AsH[0][a_kk][a_m0 + l * 8] = h;
        AsL[0][a_kk][a_m0 + l * 8] = __float2bfloat16(pa[l] - __bfloat162float(h));
    }
    *(uint4*)&BsH[0][b_kk][b_n0] = pbH;
    *(uint4*)&BsL[0][b_kk][b_n0] = pbL;
    __syncthreads();

    for (int t = 0; t < nT; t++) {
        int buf = t & 1;
        bool hasNext = (t + 1 < nT);
        if (hasNext) {
            int k0 = (t + 1) * BK;
#pragma unroll
            for (int l = 0; l < 8; l++)
                pa[l] = X[(long)(row0 + a_m0 + l * 8) * FF + k0 + a_kk];
            pbH = *(const uint4*)&WH[(long)(k0 + b_kk) * FF + col0 + b_n0];
            pbL = *(const uint4*)&WL[(long)(k0 + b_kk) * FF + col0 + b_n0];
        }
        {
            wmma::fragment<wmma::matrix_a, 16, 16, 16, __nv_bfloat16, wmma::col_major> aH[2], aL[2];
            wmma::fragment<wmma::matrix_b, 16, 16, 16, __nv_bfloat16, wmma::row_major> bH[2], bL[2];
#pragma unroll
            for (int i = 0; i < 2; i++) {
                wmma::load_matrix_sync(aH[i], &AsH[buf][0][wm + 16 * i], LDA);
                wmma::load_matrix_sync(aL[i], &AsL[buf][0][wm + 16 * i], LDA);
            }
#pragma unroll
            for (int j = 0; j < 2; j++) {
                wmma::load_matrix_sync(bH[j], &BsH[buf][0][wn + 16 * j], LDA);
                wmma::load_matrix_sync(bL[j], &BsL[buf][0][wn + 16 * j], LDA);
            }
#pragma unroll
            for (int i = 0; i < 2; i++)
#pragma unroll
                for (int j = 0; j < 2; j++) {
                    wmma::mma_sync(acc[i][j], aH[i], bH[j], acc[i][j]);
                    wmma::mma_sync(acc[i][j], aH[i], bL[j], acc[i][j]);
                    wmma::mma_sync(acc[i][j], aL[i], bH[j], acc[i][j]);
                }
        }
        if (hasNext) {
            int nbuf = 1 - buf;
#pragma unroll
            for (int l = 0; l < 8; l++) {
                __nv_bfloat16 h = __float2bfloat16(pa[l]);
                AsH[nbuf][a_kk][a_m0 + l * 8] = h;
                AsL[nbuf][a_kk][a_m0 + l * 8] = __float2bfloat16(pa[l] - __bfloat162float(h));
            }
            *(uint4*)&BsH[nbuf][b_kk][b_n0] = pbH;
            *(uint4*)&BsL[nbuf][b_kk][b_n0] = pbL;
            __syncthreads();
        }
    }
#pragma unroll
    for (int i = 0; i < 2; i++)
#pragma unroll
        for (int j = 0; j < 2; j++)
            wmma::store_matrix_sync(&Cs[wm + 16 * i][wn + 16 * j], acc[i][j], LDC,
                                    wmma::mem_row_major);
    __syncthreads();

    int tx = tid & 15, ty = tid >> 4;
#pragma unroll
    for (int i = 0; i < 8; i++) {
        int m = ty * 8 + i;
        int r = row0 + m;
        int dst = idxArr[r];
#pragma unroll
        for (int j = 0; j < 4; j++) {
            int c = col0 + tx * 4 + j;
            float aw = 1.f / (1.f + expf(-(Cs[m][tx * 4 + j] + b[c])));
            out[(long)dst * FF + c] = X[(long)r * FF + c] * aw;
        }
    }
}

// ---------------- pool scores ----------------
__global__ void scores_k(const float* __restrict__ X, const float* __restrict__ w,
                         const float* __restrict__ b, float* __restrict__ sc) {
    int warp = (blockIdx.x * blockDim.x + threadIdx.x) >> 5;
    int lane = threadIdx.x & 31;
    if (warp >= NN) return;
    const float* row = X + (long)warp * FF;
    float z = 0.f;
#pragma unroll
    for (int it = 0; it < 10; it++) {
        int t = lane + it * 32;
        z = fmaf(__ldg(row + t), __ldg(w + t), z);
    }
    for (int o = 16; o; o >>= 1) z += __shfl_down_sync(0xffffffffu, z, o);
    if (lane == 0) {
        float v = (z + b[0]) * 0.01f;
        sc[warp] = 1.f / (1.f + expf(-v));
    }
}

// ---------------- stable descending rank ----------------
__global__ void rank_kernel(const float* __restrict__ s, int* __restrict__ idxArr) {
    __shared__ int red[256];
    int i = blockIdx.x;
    int tid = threadIdx.x;
    float si = s[i];
    int cnt = 0;
    for (int j = tid; j < NN; j += 256) {
        float sj = s[j];
        cnt += (sj > si) || (sj == si && j < i);
    }
    red[tid] = cnt;
    __syncthreads();
    for (int st = 128; st > 0; st >>= 1) {
        if (tid < st) red[tid] += red[tid + st];
        __syncthreads();
    }
    if (tid == 0) idxArr[red[0]] = i;
}

// ---------------- apply pool ----------------
__global__ void pool_apply(const float* __restrict__ Xold, const float* __restrict__ sc,
                           const int* __restrict__ idxArr, const int* __restrict__ pOld,
                           int* __restrict__ pNew, int* __restrict__ pinvNew,
                           float* __restrict__ Xnew) {
    int r = blockIdx.x;
    int o = idxArr[r];
    if (threadIdx.x == 0) {
        int po = pOld[o];
        pNew[r] = po;
        pinvNew[po] = r;
    }
    float v = sc[o];
    int t = threadIdx.x;
    Xnew[(long)r * FF + t] = Xold[(long)o * FF + t] * v;
}

// ---------------- sparse GAT attention v3: 4 rows/block, 2 teams x 40 threads/row ----------------
// s1/s2 are consumed as 5 column-block partials (finalize_s folded into fill phase).
__global__ __launch_bounds__(RPB * TPW) void attn_kernel(
    const __half2* __restrict__ WhH, const float* __restrict__ sp1,
    const float* __restrict__ sp2, const int* __restrict__ cols,
    const int* __restrict__ deg, const int* __restrict__ p,
    const int* __restrict__ pinv, const float* __restrict__ resid,
    float* __restrict__ out, int applyElu, float* __restrict__ out2) {
    __shared__ float2 pk[RPB][MAXDEG];            // .x = byte offset (int bits), .y = score
    __shared__ float red[RPB][TPW];
    __shared__ __align__(16) float cmb[RPB][TPR][8];
    int tid = threadIdx.x;
    int r = tid / TPW;
    int tt = tid - r * TPW;       // 0..79
    int team = tt / TPR;          // 0,1
    int t = tt - team * TPR;      // 0..39
    int i = blockIdx.x * RPB + r;
    int orig = p[i];
    int d = deg[orig];
    float si = __ldg(sp1 + i) + __ldg(sp1 + NN + i) + __ldg(sp1 + 2 * NN + i)
             + __ldg(sp1 + 3 * NN + i) + __ldg(sp1 + 4 * NN + i);
    // fill; WhH row stride = FH*4 = 640 bytes
    for (int k = tt; k < d; k += TPW) {
        int c = __ldg(cols + (long)orig * MAXDEG + k);
        int rr = __ldg(pinv + c);
        float s2v = __ldg(sp2 + rr) + __ldg(sp2 + NN + rr) + __ldg(sp2 + 2 * NN + rr)
                  + __ldg(sp2 + 3 * NN + rr) + __ldg(sp2 + 4 * NN + rr);
        float e = si + s2v;
        e = e > 0.f ? e : 0.2f * e;   // leaky_relu(0.2)
        pk[r][k] = make_float2(__int_as_float(rr * (FH * 4)), e);
    }
    __syncthreads();
    // max reduce over 80 threads
    float m = -FLT_MAX;
    for (int k = tt; k < d; k += TPW) m = fmaxf(m, pk[r][k].y);
    red[r][tt] = m;
    __syncthreads();
#pragma unroll
    for (int s = 64; s > 0; s >>= 1) {
        if (tt < s && tt + s < TPW) red[r][tt] = fmaxf(red[r][tt], red[r][tt + s]);
        __syncthreads();
    }
    m = red[r][0];
    __syncthreads();
    // exp & sum
    float ssum = 0.f;
    for (int k = tt; k < d; k += TPW) {
        float e = __expf(pk[r][k].y - m);
        pk[r][k].y = e;
        ssum += e;
    }
    red[r][tt] = ssum;
    __syncthreads();
#pragma unroll
    for (int s = 64; s > 0; s >>= 1) {
        if (tt < s && tt + s < TPW) red[r][tt] += red[r][tt + s];
        __syncthreads();
    }
    float inv = 1.f / red[r][0];
    // aggregation: team handles neighbors k ≡ team (mod 2); 16B per thread
    const char* basep = (const char*)WhH + t * 16;
    float acc[8];
#pragma unroll
    for (int c = 0; c < 8; c++) acc[c] = 0.f;
    int k = team;
    for (; k + 4 <= d; k += 4) {
        float2 pe0 = pk[r][k];
        float2 pe1 = pk[r][k + 2];
        uint4 v0 = __ldg((const uint4*)(basep + __float_as_int(pe0.x)));
        uint4 v1 = __ldg((const uint4*)(basep + __float_as_int(pe1.x)));
        float e0 = pe0.y, e1 = pe1.y;
        {
            float2 f0 = __half22float2(*(const __half2*)&v0.x);
            float2 f1 = __half22float2(*(const __half2*)&v0.y);
            float2 f2 = __half22float2(*(const __half2*)&v0.z);
            float2 f3 = __half22float2(*(const __half2*)&v0.w);
            acc[0] = fmaf(e0, f0.x, acc[0]); acc[1] = fmaf(e0, f0.y, acc[1]);
            acc[2] = fmaf(e0, f1.x, acc[2]); acc[3] = fmaf(e0, f1.y, acc[3]);
            acc[4] = fmaf(e0, f2.x, acc[4]); acc[5] = fmaf(e0, f2.y, acc[5]);
            acc[6] = fmaf(e0, f3.x, acc[6]); acc[7] = fmaf(e0, f3.y, acc[7]);
        }
        {
            float2 f0 = __half22float2(*(const __half2*)&v1.x);
            float2 f1 = __half22float2(*(const __half2*)&v1.y);
            float2 f2 = __half22float2(*(const __half2*)&v1.z);
            float2 f3 = __half22float2(*(const __half2*)&v1.w);
            acc[0] = fmaf(e1, f0.x, acc[0]); acc[1] = fmaf(e1, f0.y, acc[1]);
            acc[2] = fmaf(e1, f1.x, acc[2]); acc[3] = fmaf(e1, f1.y, acc[3]);
            acc[4] = fmaf(e1, f2.x, acc[4]); acc[5] = fmaf(e1, f2.y, acc[5]);
            acc[6] = fmaf(e1, f3.x, acc[6]); acc[7] = fmaf(e1, f3.y, acc[7]);
        }
    }
    for (; k < d; k += 2) {
        float2 pe = pk[r][k];
        uint4 v = __ldg((const uint4*)(basep + __float_as_int(pe.x)));
        float e = pe.y;
        float2 f0 = __half22float2(*(const __half2*)&v.x);
        float2 f1 = __half22float2(*(const __half2*)&v.y);
        float2 f2 = __half22float2(*(const __half2*)&v.z);
        float2 f3 = __half22float2(*(const __half2*)&v.w);
        acc[0] = fmaf(e, f0.x, acc[0]); acc[1] = fmaf(e, f0.y, acc[1]);
        acc[2] = fmaf(e, f1.x, acc[2]); acc[3] = fmaf(e, f1.y, acc[3]);
        acc[4] = fmaf(e, f2.x, acc[4]); acc[5] = fmaf(e, f2.y, acc[5]);
        acc[6] = fmaf(e, f3.x, acc[6]); acc[7] = fmaf(e, f3.y, acc[7]);
    }
    // combine teams
    if (team == 1) {
        float4* cp = (float4*)cmb[r][t];
        cp[0] = make_float4(acc[0], acc[1], acc[2], acc[3]);
        cp[1] = make_float4(acc[4], acc[5], acc[6], acc[7]);
    }
    __syncthreads();
    if (team == 0) {
        const float4* cp = (const float4*)cmb[r][t];
        float4 c0 = cp[0], c1 = cp[1];
        acc[0] += c0.x; acc[1] += c0.y; acc[2] += c0.z; acc[3] += c0.w;
        acc[4] += c1.x; acc[5] += c1.y; acc[6] += c1.z; acc[7] += c1.w;
#pragma unroll
        for (int c = 0; c < 8; c++) {
            acc[c] *= inv;
            if (applyElu) acc[c] = acc[c] > 0.f ? acc[c] : expm1f(acc[c]);
        }
        long base = (long)i * FF + 8 * t;
        if (resid) {
            float4 r0 = *(const float4*)(resid + base);
            float4 r1 = *(const float4*)(resid + base + 4);
            acc[0] += r0.x; acc[1] += r0.y; acc[2] += r0.z; acc[3] += r0.w;
            acc[4] += r1.x; acc[5] += r1.y; acc[6] += r1.z; acc[7] += r1.w;
        }
        float4 o0 = make_float4(acc[0], acc[1], acc[2], acc[3]);
        float4 o1 = make_float4(acc[4], acc[5], acc[6], acc[7]);
        *(float4*)(out + base) = o0;
        *(float4*)(out + base + 4) = o1;
        if (out2) {
            *(float4*)(out2 + base) = o0;
            *(float4*)(out2 + base + 4) = o1;
        }
    }
}

// ---------------- host driver ----------------
static void* sym(const void* s) {
    void* p = nullptr;
    cudaGetSymbolAddress(&p, s);
    return p;
}

extern "C" void kernel_launch(void* const* d_in, const int* in_sizes, int n_in,
                              void* d_out, int out_size) {
    const float* A        = (const float*)d_in[0];
    const float* X        = (const float*)d_in[1];
    const float* start_W  = (const float*)d_in[2];
    const float* start_a  = (const float*)d_in[3];
    const float* bottom_W = (const float*)d_in[4];
    const float* bottom_a = (const float*)d_in[5];
    const float* end_W    = (const float*)d_in[6];
    const float* end_a    = (const float*)d_in[7];
    const float* down_W0  = (const float*)d_in[8];
    const float* down_a0  = (const float*)d_in[9];
    const float* up_W0    = (const float*)d_in[10];
    const float* up_a0    = (const float*)d_in[11];
    const float* pool_w0  = (const float*)d_in[12];
    const float* pool_b0  = (const float*)d_in[13];
    const float* unpool_w0= (const float*)d_in[14];
    const float* unpool_b0= (const float*)d_in[15];
    const float* down_W1  = (const float*)d_in[16];
    const float* down_a1  = (const float*)d_in[17];
    const float* up_W1    = (const float*)d_in[18];
    const float* up_a1    = (const float*)d_in[19];
    const float* pool_w1  = (const float*)d_in[20];
    const float* pool_b1  = (const float*)d_in[21];
    const float* unpool_w1= (const float*)d_in[22];
    const float* unpool_b1= (const float*)d_in[23];

    __half* WhH  = (__half*)sym(g_WhH);
    __nv_bfloat16* WH = (__nv_bfloat16*)sym(g_WH);
    __nv_bfloat16* WL = (__nv_bfloat16*)sym(g_WL);
    float* org   = (float*)sym(g_org);
    float* D0    = (float*)sym(g_D0);
    float* D1    = (float*)sym(g_D1);
    float* bA    = (float*)sym(g_bA);
    float* bB    = (float*)sym(g_bB);
    float* cent  = (float*)sym(g_cent);
    float* sp1   = (float*)sym(g_sp1);
    float* sp2   = (float*)sym(g_sp2);
    float* sc    = (float*)sym(g_sc);
    int* cols = (int*)sym(g_cols);
    int* deg  = (int*)sym(g_deg);
    int* idp  = (int*)sym(g_idp);
    int* p1   = (int*)sym(g_p1);
    int* p2   = (int*)sym(g_p2);
    int* pi1  = (int*)sym(g_pi1);
    int* pi2  = (int*)sym(g_pi2);
    int* i0   = (int*)sym(g_i0);
    int* i1   = (int*)sym(g_i1);

    float* outX = (float*)d_out;
    float* out2 = outX + (long)NN * FF;
    const __half2* WhH2 = (const __half2*)WhH;

    dim3 gemmGrid(FF / BN, NN / BM);   // (5, 64) = 320 blocks
    int attnGrid = NN / RPB;           // 1024
    int attnBlk = RPB * TPW;           // 320

    // weight split (batched)
    WTable wt;
    wt.src[0] = start_W;   wt.rows[0] = 322; wt.rowsPad[0] = 336; wt.trans[0] = 0; wt.dstOff[0] = WOFF_START;
    wt.src[1] = down_W0;   wt.rows[1] = 321; wt.rowsPad[1] = 336; wt.trans[1] = 0; wt.dstOff[1] = WOFF_DOWN0;
    wt.src[2] = down_W1;   wt.rows[2] = 321; wt.rowsPad[2] = 336; wt.trans[2] = 0; wt.dstOff[2] = WOFF_DOWN1;
    wt.src[3] = bottom_W;  wt.rows[3] = 321; wt.rowsPad[3] = 336; wt.trans[3] = 0; wt.dstOff[3] = WOFF_BOTTOM;
    wt.src[4] = up_W0;     wt.rows[4] = 321; wt.rowsPad[4] = 336; wt.trans[4] = 0; wt.dstOff[4] = WOFF_UP0;
    wt.src[5] = up_W1;     wt.rows[5] = 321; wt.rowsPad[5] = 336; wt.trans[5] = 0; wt.dstOff[5] = WOFF_UP1;
    wt.src[6] = end_W;     wt.rows[6] = 641; wt.rowsPad[6] = 656; wt.trans[6] = 0; wt.dstOff[6] = WOFF_END;
    wt.src[7] = unpool_w0; wt.rows[7] = 320; wt.rowsPad[7] = 320; wt.trans[7] = 1; wt.dstOff[7] = WOFF_UNP0;
    wt.src[8] = unpool_w1; wt.rows[8] = 320; wt.rowsPad[8] = 320; wt.trans[8] = 1; wt.dstOff[8] = WOFF_UNP1;
    dim3 splitGrid((656 * FF + 255) / 256, 9);
    split_weights<<<splitGrid, 256>>>(wt, WH, WL);

    build_adj<<<NN / 8, 256>>>(A, cols, deg, cent, idp);

    // start GAT (Ktot=322, nT=21)
    gemm_cat<<<gemmGrid, 128>>>(X, FF, nullptr, 0, 2, cent,
                                WH + (long)WOFF_START * FF, WL + (long)WOFF_START * FF,
                                322, 21, WhH, start_a, sp1, sp2);
    attn_kernel<<<attnGrid, attnBlk>>>(WhH2, sp1, sp2, cols, deg, idp, idp, nullptr, org, 1, out2);

    // down0 GAT
    gemm_cat<<<gemmGrid, 128>>>(org, FF, nullptr, 0, 1, cent,
                                WH + (long)WOFF_DOWN0 * FF, WL + (long)WOFF_DOWN0 * FF,
                                321, 21, WhH, down_a0, sp1, sp2);
    attn_kernel<<<attnGrid, attnBlk>>>(WhH2, sp1, sp2, cols, deg, idp, idp, nullptr, D0, 1, nullptr);

    // pool 0
    scores_k<<<NN / 8, 256>>>(D0, pool_w0, pool_b0, sc);
    rank_kernel<<<NN, 256>>>(sc, i0);
    pool_apply<<<NN, 320>>>(D0, sc, i0, idp, p1, pi1, bA);

    // down1 GAT
    gemm_cat<<<gemmGrid, 128>>>(bA, FF, nullptr, 0, 1, cent,
                                WH + (long)WOFF_DOWN1 * FF, WL + (long)WOFF_DOWN1 * FF,
                                321, 21, WhH, down_a1, sp1, sp2);
    attn_kernel<<<attnGrid, attnBlk>>>(WhH2, sp1, sp2, cols, deg, p1, pi1, nullptr, D1, 1, nullptr);

    // pool 1
    scores_k<<<NN / 8, 256>>>(D1, pool_w1, pool_b1, sc);
    rank_kernel<<<NN, 256>>>(sc, i1);
    pool_apply<<<NN, 320>>>(D1, sc, i1, p1, p2, pi2, bA);

    // bottom GAT
    gemm_cat<<<gemmGrid, 128>>>(bA, FF, nullptr, 0, 1, cent,
                                WH + (long)WOFF_BOTTOM * FF, WL + (long)WOFF_BOTTOM * FF,
                                321, 21, WhH, bottom_a, sp1, sp2);
    attn_kernel<<<attnGrid, attnBlk>>>(WhH2, sp1, sp2, cols, deg, p2, pi2, nullptr, bB, 1, nullptr);

    // unpool 0
    gemm_unpool<<<gemmGrid, 128>>>(bB, WH + (long)WOFF_UNP0 * FF, WL + (long)WOFF_UNP0 * FF,
                                   unpool_b0, i1, bA);

    // up0 GAT (+D1 residual fused)
    gemm_cat<<<gemmGrid, 128>>>(bA, FF, nullptr, 0, 1, cent,
                                WH + (long)WOFF_UP0 * FF, WL + (long)WOFF_UP0 * FF,
                                321, 21, WhH, up_a0, sp1, sp2);
    attn_kernel<<<attnGrid, attnBlk>>>(WhH2, sp1, sp2, cols, deg, p1, pi1, D1, bB, 1, nullptr);

    // unpool 1
    gemm_unpool<<<gemmGrid, 128>>>(bB, WH + (long)WOFF_UNP1 * FF, WL + (long)WOFF_UNP1 * FF,
                                   unpool_b1, i0, bA);

    // up1 GAT (+D0 residual fused)
    gemm_cat<<<gemmGrid, 128>>>(bA, FF, nullptr, 0, 1, cent,
                                WH + (long)WOFF_UP1 * FF, WL + (long)WOFF_UP1 * FF,
                                321, 21, WhH, up_a1, sp1, sp2);
    attn_kernel<<<attnGrid, attnBlk>>>(WhH2, sp1, sp2, cols, deg, idp, idp, D0, bB, 1, nullptr);

    // end GAT (Ktot=641, nT=41)
    gemm_cat<<<gemmGrid, 128>>>(bB, FF, org, FF, 1, cent,
                                WH + (long)WOFF_END * FF, WL + (long)WOFF_END * FF,
                                641, 41, WhH, end_a, sp1, sp2);
    attn_kernel<<<attnGrid, attnBlk>>>(WhH2, sp1, sp2, cols, deg, idp, idp, nullptr, outX, 0, nullptr);
}

// round 13
// speedup vs baseline: 1.0398x; 1.0398x over previous
#include <cuda_runtime.h>
#include <cuda_fp16.h>
#include <cuda_bf16.h>
#include <mma.h>
#include <math.h>
#include <float.h>

using namespace nvcuda;

#define NN 4096
#define FF 320
#define FH 160          // FF/2 (half2 columns)
#define MAXDEG 256
#define RPB 8           // rows per attn block
#define TPR 40          // threads per row (40 * uint4 = 320 floats)
#define NCB 5           // GEMM column blocks (FF/BN)
#define SPAD 8          // padded partial stride per node

#define BM 64
#define BN 64
#define BK 16
#define LDA 72          // smem ld for bf16 tiles
#define LDC (BN + 4)    // epilogue staging ld (floats)

// padded-row offsets for the 9 pre-split weights
#define WOFF_START   0
#define WOFF_DOWN0   336
#define WOFF_DOWN1   672
#define WOFF_BOTTOM  1008
#define WOFF_UP0     1344
#define WOFF_UP1     1680
#define WOFF_END     2016     // pad 656
#define WOFF_UNP0    2672
#define WOFF_UNP1    2992
#define WROWS_TOTAL  3312

// ---------------- scratch (static __device__ globals; no allocations) ----------------
__device__ __half g_WhH[NN * FF];
__device__ __nv_bfloat16 g_WH[WROWS_TOTAL * FF];
__device__ __nv_bfloat16 g_WL[WROWS_TOTAL * FF];
__device__ float g_org[NN * FF];
__device__ float g_D0[NN * FF];
__device__ float g_D1[NN * FF];
__device__ float g_bA[NN * FF];
__device__ float g_bB[NN * FF];
__device__ float g_cent[NN];
__device__ __align__(16) float g_sp1[NN * SPAD];
__device__ __align__(16) float g_sp2[NN * SPAD];
__device__ float g_sc[NN];
__device__ int g_cols[NN * MAXDEG];
__device__ int g_deg[NN];
__device__ int g_idp[NN];
__device__ int g_p1[NN];
__device__ int g_p2[NN];
__device__ int g_pi1[NN];
__device__ int g_pi2[NN];
__device__ int g_i0[NN];
__device__ int g_i1[NN];

// ---------------- adjacency ELL build + degree centrality + identity perm ----------------
__global__ void build_adj(const float* __restrict__ A, int* __restrict__ cols,
                          int* __restrict__ deg, float* __restrict__ cent,
                          int* __restrict__ idp) {
    int warp = (blockIdx.x * blockDim.x + threadIdx.x) >> 5;
    int lane = threadIdx.x & 31;
    if (warp >= NN) return;
    long rowoff = (long)warp * NN;
    float sum = 0.f;
    int base = 0;
    for (int c0 = 0; c0 < NN; c0 += 32) {
        float v = A[rowoff + c0 + lane];
        sum += v;
        unsigned m = __ballot_sync(0xffffffffu, v > 0.f);
        if (v > 0.f) {
            int pos = base + __popc(m & ((1u << lane) - 1u));
            if (pos < MAXDEG) cols[(long)warp * MAXDEG + pos] = c0 + lane;
        }
        base += __popc(m);
    }
    for (int o = 16; o; o >>= 1) sum += __shfl_xor_sync(0xffffffffu, sum, o);
    if (lane == 0) {
        deg[warp] = base < MAXDEG ? base : MAXDEG;
        cent[warp] = sum / (float)(NN - 1);
        idp[warp] = warp;
    }
}

// ---------------- batched weight split (hi/lo bf16, zero-padded rows, opt transpose) ----------------
struct WTable {
    const float* src[9];
    int rows[9];
    int rowsPad[9];
    int trans[9];
    int dstOff[9];
};

__global__ void split_weights(WTable wt, __nv_bfloat16* __restrict__ WH,
                              __nv_bfloat16* __restrict__ WL) {
    int w = blockIdx.y;
    int idx = blockIdx.x * blockDim.x + threadIdx.x;
    int total = wt.rowsPad[w] * FF;
    if (idx >= total) return;
    int r = idx / FF, c = idx - r * FF;
    float v = 0.f;
    if (r < wt.rows[w])
        v = wt.trans[w] ? wt.src[w][(long)c * FF + r] : wt.src[w][(long)r * FF + c];
    __nv_bfloat16 h = __float2bfloat16(v);
    __nv_bfloat16 l = __float2bfloat16(v - __bfloat162float(h));
    long o = (long)(wt.dstOff[w] + r) * FF + c;
    WH[o] = h;
    WL[o] = l;
}

// ---------------- WMMA GEMM (double-buffered): CH(half) = [X1|X2|cent*nc] @ W ----------------
// sp1/sp2 partials written at sp[r*SPAD + blockIdx.x] (contiguous per node)
__global__ __launch_bounds__(128) void gemm_cat(
    const float* __restrict__ X1, int K1,
    const float* __restrict__ X2, int K2,
    int nc, const float* __restrict__ cent,
    const __nv_bfloat16* __restrict__ WH, const __nv_bfloat16* __restrict__ WL,
    int Ktot, int nT,
    __half* __restrict__ CH, const float* __restrict__ av,
    float* __restrict__ sp1, float* __restrict__ sp2) {
    __shared__ __nv_bfloat16 AsH[2][BK][LDA], AsL[2][BK][LDA];
    __shared__ __nv_bfloat16 BsH[2][BK][LDA], BsL[2][BK][LDA];
    __shared__ float Cs[BM][LDC];
    int tid = threadIdx.x;
    int row0 = blockIdx.y * BM;
    int col0 = blockIdx.x * BN;
    int K12 = K1 + K2;

    int wid = tid >> 5;
    int wm = (wid >> 1) * 32;
    int wn = (wid & 1) * 32;

    wmma::fragment<wmma::accumulator, 16, 16, 16, float> acc[2][2];
#pragma unroll
    for (int i = 0; i < 2; i++)
#pragma unroll
        for (int j = 0; j < 2; j++) wmma::fill_fragment(acc[i][j], 0.f);

    int a_kk = tid & 15, a_m0 = tid >> 4;
    int b_kk = tid >> 3, b_n0 = (tid & 7) * 8;

    float pa[8];
    uint4 pbH, pbL;

#pragma unroll
    for (int l = 0; l < 8; l++) {
        int m = a_m0 + l * 8;
        int k = a_kk;
        int r = row0 + m;
        float v = 0.f;
        if (k < K1) v = X1[(long)r * K1 + k];
        else if (k < K12) v = X2[(long)r * K2 + (k - K1)];
        else if (k < Ktot) v = cent[r];
        pa[l] = v;
    }
    pbH = *(const uint4*)&WH[(long)b_kk * FF + col0 + b_n0];
    pbL = *(const uint4*)&WL[(long)b_kk * FF + col0 + b_n0];
#pragma unroll
    for (int l = 0; l < 8; l++) {
        __nv_bfloat16 h = __float2bfloat16(pa[l]);
        AsH[0][a_kk][a_m0 + l * 8] = h;
        AsL[0][a_kk][a_m0 + l * 8] = __float2bfloat16(pa[l] - __bfloat162float(h));
    }
    *(uint4*)&BsH[0][b_kk][b_n0] = pbH;
    *(uint4*)&BsL[0][b_kk][b_n0] = pbL;
    __syncthreads();

    for (int t = 0; t < nT; t++) {
        int buf = t & 1;
        bool hasNext = (t + 1 < nT);
        if (hasNext) {
            int k0 = (t + 1) * BK;
#pragma unroll
            for (int l = 0; l < 8; l++) {
                int m = a_m0 + l * 8;
                int k = k0 + a_kk;
                int r = row0 + m;
                float v = 0.f;
                if (k < K1) v = X1[(long)r * K1 + k];
                else if (k < K12) v = X2[(long)r * K2 + (k - K1)];
                else if (k < Ktot) v = cent[r];
                pa[l] = v;
            }
            pbH = *(const uint4*)&WH[(long)(k0 + b_kk) * FF + col0 + b_n0];
            pbL = *(const uint4*)&WL[(long)(k0 + b_kk) * FF + col0 + b_n0];
        }
        {
            wmma::fragment<wmma::matrix_a, 16, 16, 16, __nv_bfloat16, wmma::col_major> aH[2], aL[2];
            wmma::fragment<wmma::matrix_b, 16, 16, 16, __nv_bfloat16, wmma::row_major> bH[2], bL[2];
#pragma unroll
            for (int i = 0; i < 2; i++) {
                wmma::load_matrix_sync(aH[i], &AsH[buf][0][wm + 16 * i], LDA);
                wmma::load_matrix_sync(aL[i], &AsL[buf][0][wm + 16 * i], LDA);
            }
#pragma unroll
            for (int j = 0; j < 2; j++) {
                wmma::load_matrix_sync(bH[j], &BsH[buf][0][wn + 16 * j], LDA);
                wmma::load_matrix_sync(bL[j], &BsL[buf][0][wn + 16 * j], LDA);
            }
#pragma unroll
            for (int i = 0; i < 2; i++)
#pragma unroll
                for (int j = 0; j < 2; j++) {
                    wmma::mma_sync(acc[i][j], aH[i], bH[j], acc[i][j]);
                    wmma::mma_sync(acc[i][j], aH[i], bL[j], acc[i][j]);
                    wmma::mma_sync(acc[i][j], aL[i], bH[j], acc[i][j]);
                }
        }
        if (hasNext) {
            int nbuf = 1 - buf;
#pragma unroll
            for (int l = 0; l < 8; l++) {
                __nv_bfloat16 h = __float2bfloat16(pa[l]);
                AsH[nbuf][a_kk][a_m0 + l * 8] = h;
                AsL[nbuf][a_kk][a_m0 + l * 8] = __float2bfloat16(pa[l] - __bfloat162float(h));
            }
            *(uint4*)&BsH[nbuf][b_kk][b_n0] = pbH;
            *(uint4*)&BsL[nbuf][b_kk][b_n0] = pbL;
            __syncthreads();
        }
    }
#pragma unroll
    for (int i = 0; i < 2; i++)
#pragma unroll
        for (int j = 0; j < 2; j++)
            wmma::store_matrix_sync(&Cs[wm + 16 * i][wn + 16 * j], acc[i][j], LDC,
                                    wmma::mem_row_major);
    __syncthreads();

    int tx = tid & 15, ty = tid >> 4;
    float a1v[4], a2v[4];
#pragma unroll
    for (int j = 0; j < 4; j++) {
        int c = col0 + tx * 4 + j;
        a1v[j] = __ldg(av + c);
        a2v[j] = __ldg(av + FF + c);
    }
#pragma unroll
    for (int i = 0; i < 8; i++) {
        int m = ty * 8 + i;
        int r = row0 + m;
        float c0v = Cs[m][tx * 4 + 0];
        float c1v = Cs[m][tx * 4 + 1];
        float c2v = Cs[m][tx * 4 + 2];
        float c3v = Cs[m][tx * 4 + 3];
        long base = (long)r * FF + col0 + tx * 4;
        __half2* hdst = (__half2*)(CH + base);
        hdst[0] = __floats2half2_rn(c0v, c1v);
        hdst[1] = __floats2half2_rn(c2v, c3v);
        float p1 = c0v * a1v[0] + c1v * a1v[1] + c2v * a1v[2] + c3v * a1v[3];
        float p2 = c0v * a2v[0] + c1v * a2v[1] + c2v * a2v[2] + c3v * a2v[3];
#pragma unroll
        for (int o = 8; o; o >>= 1) {
            p1 += __shfl_down_sync(0xffffffffu, p1, o);
            p2 += __shfl_down_sync(0xffffffffu, p2, o);
        }
        if (tx == 0) {
            sp1[(long)r * SPAD + blockIdx.x] = p1;
            sp2[(long)r * SPAD + blockIdx.x] = p2;
        }
    }
}

// ---------------- WMMA unpool: out[idx[i]][j] = X[i][j]*sigmoid((X@W^T)[i][j]+b[j]) ----------------
__global__ __launch_bounds__(128) void gemm_unpool(
    const float* __restrict__ X,
    const __nv_bfloat16* __restrict__ WH, const __nv_bfloat16* __restrict__ WL,
    const float* __restrict__ b, const int* __restrict__ idxArr,
    float* __restrict__ out) {
    __shared__ __nv_bfloat16 AsH[2][BK][LDA], AsL[2][BK][LDA];
    __shared__ __nv_bfloat16 BsH[2][BK][LDA], BsL[2][BK][LDA];
    __shared__ float Cs[BM][LDC];
    int tid = threadIdx.x;
    int row0 = blockIdx.y * BM;
    int col0 = blockIdx.x * BN;
    const int nT = FF / BK;   // 20

    int wid = tid >> 5;
    int wm = (wid >> 1) * 32;
    int wn = (wid & 1) * 32;

    wmma::fragment<wmma::accumulator, 16, 16, 16, float> acc[2][2];
#pragma unroll
    for (int i = 0; i < 2; i++)
#pragma unroll
        for (int j = 0; j < 2; j++) wmma::fill_fragment(acc[i][j], 0.f);

    int a_kk = tid & 15, a_m0 = tid >> 4;
    int b_kk = tid >> 3, b_n0 = (tid & 7) * 8;

    float pa[8];
    uint4 pbH, pbL;
#pragma unroll
    for (int l = 0; l < 8; l++)
        pa[l] = X[(long)(row0 + a_m0 + l * 8) * FF + a_kk];
    pbH = *(const uint4*)&WH[(long)b_kk * FF + col0 + b_n0];
    pbL = *(const uint4*)&WL[(long)b_kk * FF + col0 + b_n0];
#pragma unroll
    for (int l = 0; l < 8; l++) {
        __nv_bfloat16 h = __float2bfloat16(pa[l]);
        AsH[0][a_kk][a_m0 + l * 8] = h;
        AsL[0][a_kk][a_m0 + l * 8] = __float2bfloat16(pa[l] - __bfloat162float(h));
    }
    *(uint4*)&BsH[0][b_kk][b_n0] = pbH;
    *(uint4*)&BsL[0][b_kk][b_n0] = pbL;
    __syncthreads();

    for (int t = 0; t < nT; t++) {
        int buf = t & 1;
        bool hasNext = (t + 1 < nT);
        if (hasNext) {
            int k0 = (t + 1) * BK;
#pragma unroll
            for (int l = 0; l < 8; l++)
                pa[l] = X[(long)(row0 + a_m0 + l * 8) * FF + k0 + a_kk];
            pbH = *(const uint4*)&WH[(long)(k0 + b_kk) * FF + col0 + b_n0];
            pbL = *(const uint4*)&WL[(long)(k0 + b_kk) * FF + col0 + b_n0];
        }
        {
            wmma::fragment<wmma::matrix_a, 16, 16, 16, __nv_bfloat16, wmma::col_major> aH[2], aL[2];
            wmma::fragment<wmma::matrix_b, 16, 16, 16, __nv_bfloat16, wmma::row_major> bH[2], bL[2];
#pragma unroll
            for (int i = 0; i < 2; i++) {
                wmma::load_matrix_sync(aH[i], &AsH[buf][0][wm + 16 * i], LDA);
                wmma::load_matrix_sync(aL[i], &AsL[buf][0][wm + 16 * i], LDA);
            }
#pragma unroll
            for (int j = 0; j < 2; j++) {
                wmma::load_matrix_sync(bH[j], &BsH[buf][0][wn + 16 * j], LDA);
                wmma::load_matrix_sync(bL[j], &BsL[buf][0][wn + 16 * j], LDA);
            }
#pragma unroll
            for (int i = 0; i < 2; i++)
#pragma unroll
                for (int j = 0; j < 2; j++) {
                    wmma::mma_sync(acc[i][j], aH[i], bH[j], acc[i][j]);
                    wmma::mma_sync(acc[i][j], aH[i], bL[j], acc[i][j]);
                    wmma::mma_sync(acc[i][j], aL[i], bH[j], acc[i][j]);
                }
        }
        if (hasNext) {
            int nbuf = 1 - buf;
#pragma unroll
            for (int l = 0; l < 8; l++) {
                __nv_bfloat16 h = __float2bfloat16(pa[l]);
                AsH[nbuf][a_kk][a_m0 + l * 8] = h;
                AsL[nbuf][a_kk][a_m0 + l * 8] = __float2bfloat16(pa[l] - __bfloat162float(h));
            }
            *(uint4*)&BsH[nbuf][b_kk][b_n0] = pbH;
            *(uint4*)&BsL[nbuf][b_kk][b_n0] = pbL;
            __syncthreads();
        }
    }
#pragma unroll
    for (int i = 0; i < 2; i++)
#pragma unroll
        for (int j = 0; j < 2; j++)
            wmma::store_matrix_sync(&Cs[wm + 16 * i][wn + 16 * j], acc[i][j], LDC,
                                    wmma::mem_row_major);
    __syncthreads();

    int tx = tid & 15, ty = tid >> 4;
#pragma unroll
    for (int i = 0; i < 8; i++) {
        int m = ty * 8 + i;
        int r = row0 + m;
        int dst = idxArr[r];
#pragma unroll
        for (int j = 0; j < 4; j++) {
            int c = col0 + tx * 4 + j;
            float aw = 1.f / (1.f + expf(-(Cs[m][tx * 4 + j] + b[c])));
            out[(long)dst * FF + c] = X[(long)r * FF + c] * aw;
        }
    }
}

// ---------------- pool scores ----------------
__global__ void scores_k(const float* __restrict__ X, const float* __restrict__ w,
                         const float* __restrict__ b, float* __restrict__ sc) {
    int warp = (blockIdx.x * blockDim.x + threadIdx.x) >> 5;
    int lane = threadIdx.x & 31;
    if (warp >= NN) return;
    const float* row = X + (long)warp * FF;
    float z = 0.f;
#pragma unroll
    for (int it = 0; it < 10; it++) {
        int t = lane + it * 32;
        z = fmaf(__ldg(row + t), __ldg(w + t), z);
    }
    for (int o = 16; o; o >>= 1) z += __shfl_down_sync(0xffffffffu, z, o);
    if (lane == 0) {
        float v = (z + b[0]) * 0.01f;
        sc[warp] = 1.f / (1.f + expf(-v));
    }
}

// ---------------- stable descending rank ----------------
__global__ void rank_kernel(const float* __restrict__ s, int* __restrict__ idxArr) {
    __shared__ int red[256];
    int i = blockIdx.x;
    int tid = threadIdx.x;
    float si = s[i];
    int cnt = 0;
    for (int j = tid; j < NN; j += 256) {
        float sj = s[j];
        cnt += (sj > si) || (sj == si && j < i);
    }
    red[tid] = cnt;
    __syncthreads();
    for (int st = 128; st > 0; st >>= 1) {
        if (tid < st) red[tid] += red[tid + st];
        __syncthreads();
    }
    if (tid == 0) idxArr[red[0]] = i;
}

// ---------------- apply pool ----------------
__global__ void pool_apply(const float* __restrict__ Xold, const float* __restrict__ sc,
                           const int* __restrict__ idxArr, const int* __restrict__ pOld,
                           int* __restrict__ pNew, int* __restrict__ pinvNew,
                           float* __restrict__ Xnew) {
    int r = blockIdx.x;
    int o = idxArr[r];
    if (threadIdx.x == 0) {
        int po = pOld[o];
        pNew[r] = po;
        pinvNew[po] = r;
    }
    float v = sc[o];
    int t = threadIdx.x;
    Xnew[(long)r * FF + t] = Xold[(long)o * FF + t] * v;
}

// ---------------- sparse GAT attention (R9 shape): 8 rows/block, 40 threads/row, uint4 gathers ----------------
// s1/s2 consumed as contiguous padded partials sp[i*SPAD + 0..4] (finalize folded into fill)
__global__ __launch_bounds__(RPB * TPR, 5) void attn_kernel(
    const __half2* __restrict__ WhH, const float* __restrict__ sp1,
    const float* __restrict__ sp2, const int* __restrict__ cols,
    const int* __restrict__ deg, const int* __restrict__ p,
    const int* __restrict__ pinv, const float* __restrict__ resid,
    float* __restrict__ out, int applyElu, float* __restrict__ out2) {
    __shared__ float2 pk[RPB][MAXDEG];   // .x = byte offset (int bits), .y = score
    __shared__ float red[RPB][TPR];
    int tid = threadIdx.x;
    int r = tid / TPR, t = tid - r * TPR;
    int i = blockIdx.x * RPB + r;
    int orig = p[i];
    int d = deg[orig];
    // s1[i] = sum of 5 contiguous partials (same order as old finalize_s)
    float4 qa = *(const float4*)(sp1 + (long)i * SPAD);
    float si = qa.x + qa.y + qa.z + qa.w + sp1[(long)i * SPAD + 4];
    // fill; WhH row stride = FH*4 = 640 bytes
    for (int k = t; k < d; k += TPR) {
        int c = __ldg(cols + (long)orig * MAXDEG + k);
        int rr = __ldg(pinv + c);
        float4 qb = *(const float4*)(sp2 + (long)rr * SPAD);
        float s2v = qb.x + qb.y + qb.z + qb.w + sp2[(long)rr * SPAD + 4];
        float e = si + s2v;
        e = e > 0.f ? e : 0.2f * e;   // leaky_relu(0.2)
        pk[r][k] = make_float2(__int_as_float(rr * (FH * 4)), e);
    }
    __syncthreads();
    // max reduce over 40 threads
    float m = -FLT_MAX;
    for (int k = t; k < d; k += TPR) m = fmaxf(m, pk[r][k].y);
    red[r][t] = m;
    __syncthreads();
#pragma unroll
    for (int s = 32; s > 0; s >>= 1) {
        if (t < s && t + s < TPR) red[r][t] = fmaxf(red[r][t], red[r][t + s]);
        __syncthreads();
    }
    m = red[r][0];
    __syncthreads();
    // exp & sum
    float ssum = 0.f;
    for (int k = t; k < d; k += TPR) {
        float e = __expf(pk[r][k].y - m);
        pk[r][k].y = e;
        ssum += e;
    }
    red[r][t] = ssum;
    __syncthreads();
#pragma unroll
    for (int s = 32; s > 0; s >>= 1) {
        if (t < s && t + s < TPR) red[r][t] += red[r][t + s];
        __syncthreads();
    }
    float inv = 1.f / red[r][0];
    // aggregation: thread t covers 16 bytes = 4 half2 = 8 float columns
    const char* basep = (const char*)WhH + t * 16;
    float acc[8];
#pragma unroll
    for (int c = 0; c < 8; c++) acc[c] = 0.f;
    int d2 = d & ~1;
    int k = 0;
    for (; k < d2; k += 2) {
        float2 pe0 = pk[r][k];
        float2 pe1 = pk[r][k + 1];
        uint4 v0 = __ldg((const uint4*)(basep + __float_as_int(pe0.x)));
        uint4 v1 = __ldg((const uint4*)(basep + __float_as_int(pe1.x)));
        float e0 = pe0.y, e1 = pe1.y;
        {
            float2 f0 = __half22float2(*(const __half2*)&v0.x);
            float2 f1 = __half22float2(*(const __half2*)&v0.y);
            float2 f2 = __half22float2(*(const __half2*)&v0.z);
            float2 f3 = __half22float2(*(const __half2*)&v0.w);
            acc[0] = fmaf(e0, f0.x, acc[0]); acc[1] = fmaf(e0, f0.y, acc[1]);
            acc[2] = fmaf(e0, f1.x, acc[2]); acc[3] = fmaf(e0, f1.y, acc[3]);
            acc[4] = fmaf(e0, f2.x, acc[4]); acc[5] = fmaf(e0, f2.y, acc[5]);
            acc[6] = fmaf(e0, f3.x, acc[6]); acc[7] = fmaf(e0, f3.y, acc[7]);
        }
        {
            float2 f0 = __half22float2(*(const __half2*)&v1.x);
            float2 f1 = __half22float2(*(const __half2*)&v1.y);
            float2 f2 = __half22float2(*(const __half2*)&v1.z);
            float2 f3 = __half22float2(*(const __half2*)&v1.w);
            acc[0] = fmaf(e1, f0.x, acc[0]); acc[1] = fmaf(e1, f0.y, acc[1]);
            acc[2] = fmaf(e1, f1.x, acc[2]); acc[3] = fmaf(e1, f1.y, acc[3]);
            acc[4] = fmaf(e1, f2.x, acc[4]); acc[5] = fmaf(e1, f2.y, acc[5]);
            acc[6] = fmaf(e1, f3.x, acc[6]); acc[7] = fmaf(e1, f3.y, acc[7]);
        }
    }
    for (; k < d; k++) {
        float2 pe = pk[r][k];
        uint4 v = __ldg((const uint4*)(basep + __float_as_int(pe.x)));
        float e = pe.y;
        float2 f0 = __half22float2(*(const __half2*)&v.x);
        float2 f1 = __half22float2(*(const __half2*)&v.y);
        float2 f2 = __half22float2(*(const __half2*)&v.z);
        float2 f3 = __half22float2(*(const __half2*)&v.w);
        acc[0] = fmaf(e, f0.x, acc[0]); acc[1] = fmaf(e, f0.y, acc[1]);
        acc[2] = fmaf(e, f1.x, acc[2]); acc[3] = fmaf(e, f1.y, acc[3]);
        acc[4] = fmaf(e, f2.x, acc[4]); acc[5] = fmaf(e, f2.y, acc[5]);
        acc[6] = fmaf(e, f3.x, acc[6]); acc[7] = fmaf(e, f3.y, acc[7]);
    }
#pragma unroll
    for (int c = 0; c < 8; c++) {
        acc[c] *= inv;
        if (applyElu) acc[c] = acc[c] > 0.f ? acc[c] : expm1f(acc[c]);
    }
    long base = (long)i * FF + 8 * t;
    if (resid) {
        float4 r0 = *(const float4*)(resid + base);
        float4 r1 = *(const float4*)(resid + base + 4);
        acc[0] += r0.x; acc[1] += r0.y; acc[2] += r0.z; acc[3] += r0.w;
        acc[4] += r1.x; acc[5] += r1.y; acc[6] += r1.z; acc[7] += r1.w;
    }
    float4 o0 = make_float4(acc[0], acc[1], acc[2], acc[3]);
    float4 o1 = make_float4(acc[4], acc[5], acc[6], acc[7]);
    *(float4*)(out + base) = o0;
    *(float4*)(out + base + 4) = o1;
    if (out2) {
        *(float4*)(out2 + base) = o0;
        *(float4*)(out2 + base + 4) = o1;
    }
}

// ---------------- host driver ----------------
static void* sym(const void* s) {
    void* p = nullptr;
    cudaGetSymbolAddress(&p, s);
    return p;
}

extern "C" void kernel_launch(void* const* d_in, const int* in_sizes, int n_in,
                              void* d_out, int out_size) {
    const float* A        = (const float*)d_in[0];
    const float* X        = (const float*)d_in[1];
    const float* start_W  = (const float*)d_in[2];
    const float* start_a  = (const float*)d_in[3];
    const float* bottom_W = (const float*)d_in[4];
    const float* bottom_a = (const float*)d_in[5];
    const float* end_W    = (const float*)d_in[6];
    const float* end_a    = (const float*)d_in[7];
    const float* down_W0  = (const float*)d_in[8];
    const float* down_a0  = (const float*)d_in[9];
    const float* up_W0    = (const float*)d_in[10];
    const float* up_a0    = (const float*)d_in[11];
    const float* pool_w0  = (const float*)d_in[12];
    const float* pool_b0  = (const float*)d_in[13];
    const float* unpool_w0= (const float*)d_in[14];
    const float* unpool_b0= (const float*)d_in[15];
    const float* down_W1  = (const float*)d_in[16];
    const float* down_a1  = (const float*)d_in[17];
    const float* up_W1    = (const float*)d_in[18];
    const float* up_a1    = (const float*)d_in[19];
    const float* pool_w1  = (const float*)d_in[20];
    const float* pool_b1  = (const float*)d_in[21];
    const float* unpool_w1= (const float*)d_in[22];
    const float* unpool_b1= (const float*)d_in[23];

    __half* WhH  = (__half*)sym(g_WhH);
    __nv_bfloat16* WH = (__nv_bfloat16*)sym(g_WH);
    __nv_bfloat16* WL = (__nv_bfloat16*)sym(g_WL);
    float* org   = (float*)sym(g_org);
    float* D0    = (float*)sym(g_D0);
    float* D1    = (float*)sym(g_D1);
    float* bA    = (float*)sym(g_bA);
    float* bB    = (float*)sym(g_bB);
    float* cent  = (float*)sym(g_cent);
    float* sp1   = (float*)sym(g_sp1);
    float* sp2   = (float*)sym(g_sp2);
    float* sc    = (float*)sym(g_sc);
    int* cols = (int*)sym(g_cols);
    int* deg  = (int*)sym(g_deg);
    int* idp  = (int*)sym(g_idp);
    int* p1   = (int*)sym(g_p1);
    int* p2   = (int*)sym(g_p2);
    int* pi1  = (int*)sym(g_pi1);
    int* pi2  = (int*)sym(g_pi2);
    int* i0   = (int*)sym(g_i0);
    int* i1   = (int*)sym(g_i1);

    float* outX = (float*)d_out;
    float* out2 = outX + (long)NN * FF;
    const __half2* WhH2 = (const __half2*)WhH;

    dim3 gemmGrid(FF / BN, NN / BM);   // (5, 64) = 320 blocks
    int attnGrid = NN / RPB;           // 512
    int attnBlk = RPB * TPR;           // 320

    // weight split (batched)
    WTable wt;
    wt.src[0] = start_W;   wt.rows[0] = 322; wt.rowsPad[0] = 336; wt.trans[0] = 0; wt.dstOff[0] = WOFF_START;
    wt.src[1] = down_W0;   wt.rows[1] = 321; wt.rowsPad[1] = 336; wt.trans[1] = 0; wt.dstOff[1] = WOFF_DOWN0;
    wt.src[2] = down_W1;   wt.rows[2] = 321; wt.rowsPad[2] = 336; wt.trans[2] = 0; wt.dstOff[2] = WOFF_DOWN1;
    wt.src[3] = bottom_W;  wt.rows[3] = 321; wt.rowsPad[3] = 336; wt.trans[3] = 0; wt.dstOff[3] = WOFF_BOTTOM;
    wt.src[4] = up_W0;     wt.rows[4] = 321; wt.rowsPad[4] = 336; wt.trans[4] = 0; wt.dstOff[4] = WOFF_UP0;
    wt.src[5] = up_W1;     wt.rows[5] = 321; wt.rowsPad[5] = 336; wt.trans[5] = 0; wt.dstOff[5] = WOFF_UP1;
    wt.src[6] = end_W;     wt.rows[6] = 641; wt.rowsPad[6] = 656; wt.trans[6] = 0; wt.dstOff[6] = WOFF_END;
    wt.src[7] = unpool_w0; wt.rows[7] = 320; wt.rowsPad[7] = 320; wt.trans[7] = 1; wt.dstOff[7] = WOFF_UNP0;
    wt.src[8] = unpool_w1; wt.rows[8] = 320; wt.rowsPad[8] = 320; wt.trans[8] = 1; wt.dstOff[8] = WOFF_UNP1;
    dim3 splitGrid((656 * FF + 255) / 256, 9);
    split_weights<<<splitGrid, 256>>>(wt, WH, WL);

    build_adj<<<NN / 8, 256>>>(A, cols, deg, cent, idp);

    // start GAT (Ktot=322, nT=21)
    gemm_cat<<<gemmGrid, 128>>>(X, FF, nullptr, 0, 2, cent,
                                WH + (long)WOFF_START * FF, WL + (long)WOFF_START * FF,
                                322, 21, WhH, start_a, sp1, sp2);
    attn_kernel<<<attnGrid, attnBlk>>>(WhH2, sp1, sp2, cols, deg, idp, idp, nullptr, org, 1, out2);

    // down0 GAT
    gemm_cat<<<gemmGrid, 128>>>(org, FF, nullptr, 0, 1, cent,
                                WH + (long)WOFF_DOWN0 * FF, WL + (long)WOFF_DOWN0 * FF,
                                321, 21, WhH, down_a0, sp1, sp2);
    attn_kernel<<<attnGrid, attnBlk>>>(WhH2, sp1, sp2, cols, deg, idp, idp, nullptr, D0, 1, nullptr);

    // pool 0
    scores_k<<<NN / 8, 256>>>(D0, pool_w0, pool_b0, sc);
    rank_kernel<<<NN, 256>>>(sc, i0);
    pool_apply<<<NN, 320>>>(D0, sc, i0, idp, p1, pi1, bA);

    // down1 GAT
    gemm_cat<<<gemmGrid, 128>>>(bA, FF, nullptr, 0, 1, cent,
                                WH + (long)WOFF_DOWN1 * FF, WL + (long)WOFF_DOWN1 * FF,
                                321, 21, WhH, down_a1, sp1, sp2);
    attn_kernel<<<attnGrid, attnBlk>>>(WhH2, sp1, sp2, cols, deg, p1, pi1, nullptr, D1, 1, nullptr);

    // pool 1
    scores_k<<<NN / 8, 256>>>(D1, pool_w1, pool_b1, sc);
    rank_kernel<<<NN, 256>>>(sc, i1);
    pool_apply<<<NN, 320>>>(D1, sc, i1, p1, p2, pi2, bA);

    // bottom GAT
    gemm_cat<<<gemmGrid, 128>>>(bA, FF, nullptr, 0, 1, cent,
                                WH + (long)WOFF_BOTTOM * FF, WL + (long)WOFF_BOTTOM * FF,
                                321, 21, WhH, bottom_a, sp1, sp2);
    attn_kernel<<<attnGrid, attnBlk>>>(WhH2, sp1, sp2, cols, deg, p2, pi2, nullptr, bB, 1, nullptr);

    // unpool 0
    gemm_unpool<<<gemmGrid, 128>>>(bB, WH + (long)WOFF_UNP0 * FF, WL + (long)WOFF_UNP0 * FF,
                                   unpool_b0, i1, bA);

    // up0 GAT (+D1 residual fused)
    gemm_cat<<<gemmGrid, 128>>>(bA, FF, nullptr, 0, 1, cent,
                                WH + (long)WOFF_UP0 * FF, WL + (long)WOFF_UP0 * FF,
                                321, 21, WhH, up_a0, sp1, sp2);
    attn_kernel<<<attnGrid, attnBlk>>>(WhH2, sp1, sp2, cols, deg, p1, pi1, D1, bB, 1, nullptr);

    // unpool 1
    gemm_unpool<<<gemmGrid, 128>>>(bB, WH + (long)WOFF_UNP1 * FF, WL + (long)WOFF_UNP1 * FF,
                                   unpool_b1, i0, bA);

    // up1 GAT (+D0 residual fused)
    gemm_cat<<<gemmGrid, 128>>>(bA, FF, nullptr, 0, 1, cent,
                                WH + (long)WOFF_UP1 * FF, WL + (long)WOFF_UP1 * FF,
                                321, 21, WhH, up_a1, sp1, sp2);
    attn_kernel<<<attnGrid, attnBlk>>>(WhH2, sp1, sp2, cols, deg, idp, idp, D0, bB, 1, nullptr);

    // end GAT (Ktot=641, nT=41)
    gemm_cat<<<gemmGrid, 128>>>(bB, FF, org, FF, 1, cent,
                                WH + (long)WOFF_END * FF, WL + (long)WOFF_END * FF,
                                641, 41, WhH, end_a, sp1, sp2);
    attn_kernel<<<attnGrid, attnBlk>>>(WhH2, sp1, sp2, cols, deg, idp, idp, nullptr, outX, 0, nullptr);
}